// round 16
// baseline (speedup 1.0000x reference)
#include <cuda_runtime.h>
#include <cuda_fp16.h>
#include <cstdint>

// ---------------------------------------------------------------------------
// Attention_21474836480706: B=4, N=1024, H=16, D=72, HID=1152 (fp32)
// R16: gemm restructured BM=256/BN=128, 64x64 warp tiles (32 MMA : 8 ldsm),
// 3-stage cp.async. Flash + prep unchanged from R15. Same math/accuracy.
// ---------------------------------------------------------------------------

namespace {
constexpr int Bb    = 4;
constexpr int Nn    = 1024;
constexpr int Hh    = 16;
constexpr int Dd    = 72;
constexpr int DP    = 80;
constexpr int HID   = 1152;
constexpr int ATT   = Hh * Dd;        // 1152
constexpr int MTOK  = Bb * Nn;        // 4096
constexpr int QKVN  = 3 * ATT;        // 3456
constexpr int BHEAD = Bb * Hh;        // 64
}

// ------------------------------ scratch ------------------------------------
__device__ __align__(16) __half g_qh[(size_t)BHEAD * Nn * DP];   // Q fp16 (pre-scaled)
__device__ __align__(16) __half g_kh[(size_t)BHEAD * Nn * DP];   // K fp16
__device__ __align__(16) __half g_vth[(size_t)BHEAD * Dd * Nn];  // V^T fp16

__device__ __align__(16) __half g_xa[(size_t)MTOK * HID];        // x fp16
__device__ __align__(16) __half g_oa[(size_t)MTOK * HID];        // attn out fp16
__device__ __align__(16) __half g_wqkvt[(size_t)QKVN * HID];     // W_qkv^T fp16
__device__ __align__(16) __half g_wot[(size_t)HID * HID];        // W_out^T fp16

// --------------------------- helpers ---------------------------------------
__device__ __forceinline__ uint32_t smem_u32(const void* p) {
    uint32_t a;
    asm("{ .reg .u64 t; cvta.to.shared.u64 t, %1; cvt.u32.u64 %0, t; }" : "=r"(a) : "l"(p));
    return a;
}
__device__ __forceinline__ void cp16(uint32_t s, const void* g) {
    asm volatile("cp.async.cg.shared.global [%0], [%1], 16;" :: "r"(s), "l"(g));
}
#define CP_COMMIT() asm volatile("cp.async.commit_group;" ::: "memory")
#define CP_WAIT(n)  asm volatile("cp.async.wait_group %0;" :: "n"(n) : "memory")

__device__ __forceinline__ void ldsm4(uint32_t& r0, uint32_t& r1, uint32_t& r2, uint32_t& r3,
                                      uint32_t a) {
    asm volatile("ldmatrix.sync.aligned.m8n8.x4.shared.b16 {%0,%1,%2,%3}, [%4];"
                 : "=r"(r0), "=r"(r1), "=r"(r2), "=r"(r3) : "r"(a));
}
__device__ __forceinline__ void ldsm2(uint32_t& r0, uint32_t& r1, uint32_t a) {
    asm volatile("ldmatrix.sync.aligned.m8n8.x2.shared.b16 {%0,%1}, [%2];"
                 : "=r"(r0), "=r"(r1) : "r"(a));
}
__device__ __forceinline__ void mma16816(float* d, const uint32_t* a, const uint32_t* b) {
    asm volatile(
        "mma.sync.aligned.m16n8k16.row.col.f32.f16.f16.f32 "
        "{%0,%1,%2,%3}, {%4,%5,%6,%7}, {%8,%9}, {%0,%1,%2,%3};"
        : "+f"(d[0]), "+f"(d[1]), "+f"(d[2]), "+f"(d[3])
        : "r"(a[0]), "r"(a[1]), "r"(a[2]), "r"(a[3]), "r"(b[0]), "r"(b[1]));
}
__device__ __forceinline__ uint32_t pack2(float a, float b) {
    __half2 h2 = __halves2half2(__float2half(a), __float2half(b));
    return *reinterpret_cast<uint32_t*>(&h2);
}

// ---------------------------------------------------------------------------
// Fused prep: region-dispatched on blockIdx.x.
// ---------------------------------------------------------------------------
namespace {
constexpr int NB_X  = MTOK * HID / 4 / 256;        // 4608
constexpr int NB_WQ = (QKVN / 32) * (HID / 32);    // 3888
constexpr int NB_WO = (HID / 32) * (HID / 32);     // 1296
constexpr int NB_PREP = NB_X + NB_WQ + NB_WO;      // 9792
}

__global__ __launch_bounds__(256) void k_prep(const float* __restrict__ x,
                                              const float* __restrict__ w_qkv,
                                              const float* __restrict__ w_out) {
    __shared__ float t[32][33];
    const int bid = blockIdx.x;
    const int tid = threadIdx.x;

    if (bid < NB_X) {
        const int i = bid * 256 + tid;
        float4 v = reinterpret_cast<const float4*>(x)[i];
        reinterpret_cast<__half2*>(g_xa)[2 * i] =
            __halves2half2(__float2half(v.x), __float2half(v.y));
        reinterpret_cast<__half2*>(g_xa)[2 * i + 1] =
            __halves2half2(__float2half(v.z), __float2half(v.w));
        if (i < BHEAD * Nn) {
            const size_t o = (size_t)i * DP + Dd;
            const uint4 z = make_uint4(0, 0, 0, 0);
            *reinterpret_cast<uint4*>(&g_qh[o]) = z;
            *reinterpret_cast<uint4*>(&g_kh[o]) = z;
        }
        return;
    }

    const bool isWQ = (bid < NB_X + NB_WQ);
    const int  b2   = isWQ ? (bid - NB_X) : (bid - NB_X - NB_WQ);
    const int  NC   = isWQ ? QKVN : HID;
    const int  nTil = NC / 32;
    const int  n0 = (b2 % nTil) * 32;
    const int  k0 = (b2 / nTil) * 32;
    const float* W = isWQ ? w_qkv : w_out;
    __half* Wt = isWQ ? g_wqkvt : g_wot;

    const int tx = tid & 31, ty = tid >> 5;
#pragma unroll
    for (int i = 0; i < 4; ++i)
        t[ty * 4 + i][tx] = W[(size_t)(k0 + ty * 4 + i) * NC + n0 + tx];
    __syncthreads();
#pragma unroll
    for (int i = 0; i < 4; ++i)
        Wt[(size_t)(n0 + ty * 4 + i) * HID + k0 + tx] = __float2half(t[tx][ty * 4 + i]);
}

// ---------------------------------------------------------------------------
// HMMA GEMM (projections): BM=256, BN=128, GBK=64, 64x64 warp tiles,
// 3-stage cp.async pipeline, 1 CTA/SM.
// ---------------------------------------------------------------------------
namespace {
constexpr int GBM = 256, GBN = 128, GBK = 64, GLDS = 72;
constexpr int ATILE = GBM * GLDS;                 // 18432 elems
constexpr int BTILE = GBN * GLDS;                 // 9216 elems
constexpr int GSTAGE = ATILE + BTILE;             // 27648 elems
constexpr int GEMM_SMEM = 3 * GSTAGE * 2;         // 165888 B
}

template <int MODE>
__global__ __launch_bounds__(256) void k_gemm(const float* __restrict__ bias,
                                              float* __restrict__ Cout) {
    extern __shared__ __half gsm[];

    const int tid  = threadIdx.x;
    const int warp = tid >> 5, lane = tid & 31;
    const int wm = (warp & 3) * 64;       // 0,64,128,192
    const int wn = (warp >> 2) * 64;      // 0,64
    const int gi  = lane >> 2;
    const int tig = lane & 3;
    const int m0 = blockIdx.y * GBM;
    const int n0 = blockIdx.x * GBN;

    const int lane7 = lane & 7;
    const int aRow = lane7 + ((lane & 8) ? 8 : 0);
    const int aK   = (lane & 16) ? 8 : 0;
    const int bRow = lane7 + ((lane & 16) ? 8 : 0);
    const int bK   = (lane & 8) ? 8 : 0;

    const __half* __restrict__ Ah = MODE ? g_oa : g_xa;
    const __half* __restrict__ Bh = MODE ? g_wot : g_wqkvt;

    auto issue_tile = [&](int kt, int stage) {
        __half* base = gsm + stage * GSTAGE;
        const int kk = kt * GBK;
#pragma unroll
        for (int c = 0; c < 8; ++c) {              // A: 256 rows x 8 chunks
            const int chunk = tid + c * 256;       // 0..2047
            const int row = chunk >> 3;
            const int kc  = chunk & 7;
            cp16(smem_u32(base + row * GLDS + kc * 8),
                 Ah + (size_t)(m0 + row) * HID + kk + kc * 8);
        }
#pragma unroll
        for (int c = 0; c < 4; ++c) {              // B: 128 rows x 8 chunks
            const int chunk = tid + c * 256;       // 0..1023
            const int row = chunk >> 3;
            const int kc  = chunk & 7;
            cp16(smem_u32(base + ATILE + row * GLDS + kc * 8),
                 Bh + (size_t)(n0 + row) * HID + kk + kc * 8);
        }
        CP_COMMIT();
    };

    float acc[4][8][4] = {};
    constexpr int NT = HID / GBK;   // 18

    issue_tile(0, 0);
    issue_tile(1, 1);

    int st = 0;
    for (int t = 0; t < NT; ++t) {
        if (t + 2 < NT) {
            const int s2 = (st + 2) % 3;
            issue_tile(t + 2, s2);
            CP_WAIT(2);
        } else if (t + 1 < NT) {
            CP_WAIT(1);
        } else {
            CP_WAIT(0);
        }
        __syncthreads();

        const uint32_t uA = smem_u32(gsm + st * GSTAGE);
        const uint32_t uB = uA + ATILE * 2;

#pragma unroll
        for (int ks = 0; ks < GBK; ks += 16) {
            uint32_t b[8][2];
#pragma unroll
            for (int np = 0; np < 4; ++np) {
                const uint32_t off = ((wn + np * 16 + bRow) * GLDS + ks + bK) * 2;
                ldsm4(b[2 * np][0], b[2 * np][1], b[2 * np + 1][0], b[2 * np + 1][1],
                      uB + off);
            }
#pragma unroll
            for (int mf = 0; mf < 4; ++mf) {
                uint32_t ah[4];
                const uint32_t off = ((wm + mf * 16 + aRow) * GLDS + ks + aK) * 2;
                ldsm4(ah[0], ah[1], ah[2], ah[3], uA + off);
#pragma unroll
                for (int nf = 0; nf < 8; ++nf)
                    mma16816(acc[mf][nf], ah, b[nf]);
            }
        }
        __syncthreads();
        st = (st + 1) % 3;
    }

    const float qscale = 0.11785113019775793f;  // 1/sqrt(72)
#pragma unroll
    for (int mf = 0; mf < 4; ++mf) {
#pragma unroll
        for (int nf = 0; nf < 8; ++nf) {
            const int row = m0 + wm + mf * 16 + gi;
            const int col = n0 + wn + nf * 8 + tig * 2;
            const float b0 = bias[col], b1 = bias[col + 1];
            float x0 = acc[mf][nf][0] + b0, y0 = acc[mf][nf][1] + b1;
            float x1 = acc[mf][nf][2] + b0, y1 = acc[mf][nf][3] + b1;
            if (MODE == 0) {
                const int which = n0 / ATT;
                const int rem = col - which * ATT;
                const int h = rem / Dd, d = rem - h * Dd;
                const int bb = row >> 10, tok = row & 1023;
                const int bh = bb * Hh + h;
                if (which < 2) {
                    if (which == 0) { x0 *= qscale; y0 *= qscale; x1 *= qscale; y1 *= qscale; }
                    __half* dst = which ? g_kh : g_qh;
                    const size_t o0 = ((size_t)bh * Nn + tok) * DP + d;
                    const size_t o1 = o0 + 8 * DP;
                    *reinterpret_cast<__half2*>(&dst[o0]) =
                        __halves2half2(__float2half(x0), __float2half(y0));
                    *reinterpret_cast<__half2*>(&dst[o1]) =
                        __halves2half2(__float2half(x1), __float2half(y1));
                } else {
                    const size_t b0o = ((size_t)bh * Dd + d) * Nn + tok;
                    const size_t b1o = b0o + Nn;
                    g_vth[b0o]     = __float2half(x0);
                    g_vth[b1o]     = __float2half(y0);
                    g_vth[b0o + 8] = __float2half(x1);
                    g_vth[b1o + 8] = __float2half(y1);
                }
            } else {
                *reinterpret_cast<float2*>(&Cout[(size_t)row * HID + col]) = make_float2(x0, y0);
                *reinterpret_cast<float2*>(&Cout[(size_t)(row + 8) * HID + col]) = make_float2(x1, y1);
            }
        }
    }
}

// ---------------------------------------------------------------------------
// Flash attention (unchanged from R15): single-pass fp16 throughout.
// ---------------------------------------------------------------------------
namespace {
constexpr int LDSK  = 88;
constexpr int LDSV  = 72;
constexpr int KROWS = 64;
constexpr int QELE  = 128 * LDSK;
constexpr int KELE  = KROWS * LDSK;
constexpr int VELE  = Dd * LDSV;
constexpr int FLASH_SMEM = (QELE + KELE + VELE) * 2;   // 44160 B
}

__global__ __launch_bounds__(256, 2) void k_flash() {
    extern __shared__ __half sm[];
    __half* sQh = sm;
    __half* sKh = sm + QELE;
    __half* sVh = sm + QELE + KELE;

    const int tid  = threadIdx.x;
    const int warp = tid >> 5, lane = tid & 31;
    const int wm  = warp * 16;
    const int gi  = lane >> 2;
    const int tig = lane & 3;
    const int bh = blockIdx.y;
    const int m0 = blockIdx.x * 128;

    const int lane7 = lane & 7;
    const int aRow = lane7 + ((lane & 8) ? 8 : 0);
    const int aK   = (lane & 16) ? 8 : 0;
    const int bRow = lane7 + ((lane & 16) ? 8 : 0);
    const int bK   = (lane & 8) ? 8 : 0;

    const uint32_t uQh = smem_u32(sQh);
    const uint32_t uKh = smem_u32(sKh);
    const uint32_t uVh = smem_u32(sVh);

    const __half* __restrict__ Qh = g_qh + (size_t)bh * Nn * DP;
    const __half* __restrict__ Kh = g_kh + (size_t)bh * Nn * DP;
    const __half* __restrict__ Vh = g_vth + (size_t)bh * Dd * Nn;

    auto issueK = [&](int kt) {
        const int nn = kt * KROWS;
#pragma unroll
        for (int c = 0; c < 3; ++c) {
            const int chunk = tid + c * 256;
            if (chunk < KROWS * 10) {
                const int row = chunk / 10;
                const int kc  = chunk - row * 10;
                cp16(smem_u32(sKh + row * LDSK + kc * 8),
                     Kh + (size_t)(nn + row) * DP + kc * 8);
            }
        }
        CP_COMMIT();
    };
    auto issueV = [&](int kt) {
        const int nn = kt * KROWS;
#pragma unroll
        for (int c = 0; c < 3; ++c) {
            const int chunk = tid + c * 256;
            if (chunk < Dd * 8) {
                const int row = chunk >> 3;
                const int kc  = chunk & 7;
                cp16(smem_u32(sVh + row * LDSV + kc * 8),
                     Vh + (size_t)row * Nn + nn + kc * 8);
            }
        }
        CP_COMMIT();
    };

    issueK(0);
#pragma unroll
    for (int c = 0; c < 5; ++c) {
        const int chunk = tid + c * 256;
        const int row = chunk / 10;
        const int kc  = chunk - row * 10;
        const size_t gq = (size_t)(m0 + row) * DP + kc * 8;
        *reinterpret_cast<uint4*>(&sQh[row * LDSK + kc * 8]) =
            *reinterpret_cast<const uint4*>(&Qh[gq]);
    }

    float m_run0 = -3.4e38f, m_run1 = -3.4e38f;
    float l_run0 = 0.f, l_run1 = 0.f;
    float o[9][4] = {};

    for (int kt = 0; kt < Nn / KROWS; ++kt) {
        CP_WAIT(0);
        __syncthreads();

        issueV(kt);

        float s[8][4];
#pragma unroll
        for (int nf = 0; nf < 8; ++nf)
            s[nf][0] = s[nf][1] = s[nf][2] = s[nf][3] = 0.f;
#pragma unroll
        for (int ks = 0; ks < DP; ks += 16) {
            uint32_t aH[4], b[2][2];
            const uint32_t aoff = ((wm + aRow) * LDSK + ks + aK) * 2;
            ldsm4(aH[0], aH[1], aH[2], aH[3], uQh + aoff);
#pragma unroll
            for (int np = 0; np < 4; ++np) {
                const uint32_t boff = ((np * 16 + bRow) * LDSK + ks + bK) * 2;
                ldsm4(b[0][0], b[0][1], b[1][0], b[1][1], uKh + boff);
                mma16816(s[2 * np],     aH, b[0]);
                mma16816(s[2 * np + 1], aH, b[1]);
            }
        }

        float mt0 = -3.4e38f, mt1 = -3.4e38f;
#pragma unroll
        for (int nf = 0; nf < 8; ++nf) {
            mt0 = fmaxf(mt0, fmaxf(s[nf][0], s[nf][1]));
            mt1 = fmaxf(mt1, fmaxf(s[nf][2], s[nf][3]));
        }
        mt0 = fmaxf(mt0, __shfl_xor_sync(0xffffffffu, mt0, 1));
        mt0 = fmaxf(mt0, __shfl_xor_sync(0xffffffffu, mt0, 2));
        mt1 = fmaxf(mt1, __shfl_xor_sync(0xffffffffu, mt1, 1));
        mt1 = fmaxf(mt1, __shfl_xor_sync(0xffffffffu, mt1, 2));
        const float mn0 = fmaxf(m_run0, mt0);
        const float mn1 = fmaxf(m_run1, mt1);
        const float sc0 = __expf(m_run0 - mn0);
        const float sc1 = __expf(m_run1 - mn1);
        m_run0 = mn0;
        m_run1 = mn1;
#pragma unroll
        for (int nf = 0; nf < 9; ++nf) {
            o[nf][0] *= sc0; o[nf][1] *= sc0;
            o[nf][2] *= sc1; o[nf][3] *= sc1;
        }

        CP_WAIT(0);
        __syncthreads();

        if (kt + 1 < Nn / KROWS) issueK(kt + 1);

        float ps0 = 0.f, ps1 = 0.f;
#pragma unroll
        for (int kc = 0; kc < 4; ++kc) {
            const int nf0 = 2 * kc, nf1 = 2 * kc + 1;
            const float p00 = __expf(s[nf0][0] - mn0), p01 = __expf(s[nf0][1] - mn0);
            const float p02 = __expf(s[nf0][2] - mn1), p03 = __expf(s[nf0][3] - mn1);
            const float p10 = __expf(s[nf1][0] - mn0), p11 = __expf(s[nf1][1] - mn0);
            const float p12 = __expf(s[nf1][2] - mn1), p13 = __expf(s[nf1][3] - mn1);
            ps0 += p00 + p01 + p10 + p11;
            ps1 += p02 + p03 + p12 + p13;
            uint32_t pH[4];
            pH[0] = pack2(p00, p01);
            pH[1] = pack2(p02, p03);
            pH[2] = pack2(p10, p11);
            pH[3] = pack2(p12, p13);

            uint32_t b[9][2];
#pragma unroll
            for (int np = 0; np < 4; ++np) {
                const uint32_t off = ((np * 16 + bRow) * LDSV + kc * 16 + bK) * 2;
                ldsm4(b[2 * np][0], b[2 * np][1], b[2 * np + 1][0], b[2 * np + 1][1], uVh + off);
            }
            {
                const uint32_t off = ((64 + lane7) * LDSV + kc * 16 + bK) * 2;
                ldsm2(b[8][0], b[8][1], uVh + off);
            }
#pragma unroll
            for (int nf = 0; nf < 9; ++nf)
                mma16816(o[nf], pH, b[nf]);
        }
        ps0 += __shfl_xor_sync(0xffffffffu, ps0, 1);
        ps0 += __shfl_xor_sync(0xffffffffu, ps0, 2);
        ps1 += __shfl_xor_sync(0xffffffffu, ps1, 1);
        ps1 += __shfl_xor_sync(0xffffffffu, ps1, 2);
        l_run0 = l_run0 * sc0 + ps0;
        l_run1 = l_run1 * sc1 + ps1;
    }

    const float inv0 = 1.0f / l_run0;
    const float inv1 = 1.0f / l_run1;
    const int b = bh >> 4;
    const int h = bh & 15;
    const int tok0 = m0 + wm + gi;
#pragma unroll
    for (int nf = 0; nf < 9; ++nf) {
        const int col = nf * 8 + tig * 2;
        const size_t o0 = ((size_t)(b * Nn + tok0)) * HID + h * Dd + col;
        const size_t o1 = ((size_t)(b * Nn + tok0 + 8)) * HID + h * Dd + col;
        *reinterpret_cast<__half2*>(&g_oa[o0]) =
            __halves2half2(__float2half(o[nf][0] * inv0), __float2half(o[nf][1] * inv0));
        *reinterpret_cast<__half2*>(&g_oa[o1]) =
            __halves2half2(__float2half(o[nf][2] * inv1), __float2half(o[nf][3] * inv1));
    }
}

// ---------------------------------------------------------------------------
extern "C" void kernel_launch(void* const* d_in, const int* in_sizes, int n_in,
                              void* d_out, int out_size) {
    const float* x     = (const float*)d_in[0];
    const float* w_qkv = (const float*)d_in[1];
    const float* b_qkv = (const float*)d_in[2];
    const float* w_out = (const float*)d_in[3];
    const float* b_out = (const float*)d_in[4];
    float* out = (float*)d_out;

    cudaFuncSetAttribute(k_flash, cudaFuncAttributeMaxDynamicSharedMemorySize, FLASH_SMEM);
    cudaFuncSetAttribute(k_gemm<0>, cudaFuncAttributeMaxDynamicSharedMemorySize, GEMM_SMEM);
    cudaFuncSetAttribute(k_gemm<1>, cudaFuncAttributeMaxDynamicSharedMemorySize, GEMM_SMEM);

    // fused prep
    k_prep<<<NB_PREP, 256>>>(x, w_qkv, w_out);

    // 1. QKV projection -> Q(scaled)/K fp16 (padded), V^T fp16
    k_gemm<0><<<dim3(QKVN / 128, MTOK / 256), 256, GEMM_SMEM>>>(b_qkv, nullptr);

    // 2. fused flash attention -> g_oa fp16
    k_flash<<<dim3(Nn / 128, BHEAD), 256, FLASH_SMEM>>>();

    // 3. output projection
    k_gemm<1><<<dim3(HID / 128, MTOK / 256), 256, GEMM_SMEM>>>(b_out, out);
}

// round 17
// speedup vs baseline: 1.0508x; 1.0508x over previous
#include <cuda_runtime.h>
#include <cuda_fp16.h>
#include <cstdint>

// ---------------------------------------------------------------------------
// Attention_21474836480706: B=4, N=1024, H=16, D=72, HID=1152 (fp32)
// R17: gemm reverted to R15 geometry (128x128, GBK=64, 2 CTAs/SM) + 3-stage
// cp.async pipeline (110.6 KB/CTA, dual residency kept). Flash/prep as R15.
// ---------------------------------------------------------------------------

namespace {
constexpr int Bb    = 4;
constexpr int Nn    = 1024;
constexpr int Hh    = 16;
constexpr int Dd    = 72;
constexpr int DP    = 80;
constexpr int HID   = 1152;
constexpr int ATT   = Hh * Dd;        // 1152
constexpr int MTOK  = Bb * Nn;        // 4096
constexpr int QKVN  = 3 * ATT;        // 3456
constexpr int BHEAD = Bb * Hh;        // 64
}

// ------------------------------ scratch ------------------------------------
__device__ __align__(16) __half g_qh[(size_t)BHEAD * Nn * DP];   // Q fp16 (pre-scaled)
__device__ __align__(16) __half g_kh[(size_t)BHEAD * Nn * DP];   // K fp16
__device__ __align__(16) __half g_vth[(size_t)BHEAD * Dd * Nn];  // V^T fp16

__device__ __align__(16) __half g_xa[(size_t)MTOK * HID];        // x fp16
__device__ __align__(16) __half g_oa[(size_t)MTOK * HID];        // attn out fp16
__device__ __align__(16) __half g_wqkvt[(size_t)QKVN * HID];     // W_qkv^T fp16
__device__ __align__(16) __half g_wot[(size_t)HID * HID];        // W_out^T fp16

// --------------------------- helpers ---------------------------------------
__device__ __forceinline__ uint32_t smem_u32(const void* p) {
    uint32_t a;
    asm("{ .reg .u64 t; cvta.to.shared.u64 t, %1; cvt.u32.u64 %0, t; }" : "=r"(a) : "l"(p));
    return a;
}
__device__ __forceinline__ void cp16(uint32_t s, const void* g) {
    asm volatile("cp.async.cg.shared.global [%0], [%1], 16;" :: "r"(s), "l"(g));
}
#define CP_COMMIT() asm volatile("cp.async.commit_group;" ::: "memory")
#define CP_WAIT(n)  asm volatile("cp.async.wait_group %0;" :: "n"(n) : "memory")

__device__ __forceinline__ void ldsm4(uint32_t& r0, uint32_t& r1, uint32_t& r2, uint32_t& r3,
                                      uint32_t a) {
    asm volatile("ldmatrix.sync.aligned.m8n8.x4.shared.b16 {%0,%1,%2,%3}, [%4];"
                 : "=r"(r0), "=r"(r1), "=r"(r2), "=r"(r3) : "r"(a));
}
__device__ __forceinline__ void ldsm2(uint32_t& r0, uint32_t& r1, uint32_t a) {
    asm volatile("ldmatrix.sync.aligned.m8n8.x2.shared.b16 {%0,%1}, [%2];"
                 : "=r"(r0), "=r"(r1) : "r"(a));
}
__device__ __forceinline__ void mma16816(float* d, const uint32_t* a, const uint32_t* b) {
    asm volatile(
        "mma.sync.aligned.m16n8k16.row.col.f32.f16.f16.f32 "
        "{%0,%1,%2,%3}, {%4,%5,%6,%7}, {%8,%9}, {%0,%1,%2,%3};"
        : "+f"(d[0]), "+f"(d[1]), "+f"(d[2]), "+f"(d[3])
        : "r"(a[0]), "r"(a[1]), "r"(a[2]), "r"(a[3]), "r"(b[0]), "r"(b[1]));
}
__device__ __forceinline__ uint32_t pack2(float a, float b) {
    __half2 h2 = __halves2half2(__float2half(a), __float2half(b));
    return *reinterpret_cast<uint32_t*>(&h2);
}

// ---------------------------------------------------------------------------
// Fused prep: region-dispatched on blockIdx.x.
// ---------------------------------------------------------------------------
namespace {
constexpr int NB_X  = MTOK * HID / 4 / 256;        // 4608
constexpr int NB_WQ = (QKVN / 32) * (HID / 32);    // 3888
constexpr int NB_WO = (HID / 32) * (HID / 32);     // 1296
constexpr int NB_PREP = NB_X + NB_WQ + NB_WO;      // 9792
}

__global__ __launch_bounds__(256) void k_prep(const float* __restrict__ x,
                                              const float* __restrict__ w_qkv,
                                              const float* __restrict__ w_out) {
    __shared__ float t[32][33];
    const int bid = blockIdx.x;
    const int tid = threadIdx.x;

    if (bid < NB_X) {
        const int i = bid * 256 + tid;
        float4 v = reinterpret_cast<const float4*>(x)[i];
        reinterpret_cast<__half2*>(g_xa)[2 * i] =
            __halves2half2(__float2half(v.x), __float2half(v.y));
        reinterpret_cast<__half2*>(g_xa)[2 * i + 1] =
            __halves2half2(__float2half(v.z), __float2half(v.w));
        if (i < BHEAD * Nn) {
            const size_t o = (size_t)i * DP + Dd;
            const uint4 z = make_uint4(0, 0, 0, 0);
            *reinterpret_cast<uint4*>(&g_qh[o]) = z;
            *reinterpret_cast<uint4*>(&g_kh[o]) = z;
        }
        return;
    }

    const bool isWQ = (bid < NB_X + NB_WQ);
    const int  b2   = isWQ ? (bid - NB_X) : (bid - NB_X - NB_WQ);
    const int  NC   = isWQ ? QKVN : HID;
    const int  nTil = NC / 32;
    const int  n0 = (b2 % nTil) * 32;
    const int  k0 = (b2 / nTil) * 32;
    const float* W = isWQ ? w_qkv : w_out;
    __half* Wt = isWQ ? g_wqkvt : g_wot;

    const int tx = tid & 31, ty = tid >> 5;
#pragma unroll
    for (int i = 0; i < 4; ++i)
        t[ty * 4 + i][tx] = W[(size_t)(k0 + ty * 4 + i) * NC + n0 + tx];
    __syncthreads();
#pragma unroll
    for (int i = 0; i < 4; ++i)
        Wt[(size_t)(n0 + ty * 4 + i) * HID + k0 + tx] = __float2half(t[tx][ty * 4 + i]);
}

// ---------------------------------------------------------------------------
// HMMA GEMM (projections): 128x128, GBK=64, 3-stage cp.async, 2 CTAs/SM.
// ---------------------------------------------------------------------------
namespace {
constexpr int GBM = 128, GBK = 64, GLDS = 72;
constexpr int GTILE = GBM * GLDS;                 // 9216 elems
constexpr int GSTAGE = 2 * GTILE;                 // A + B per stage
constexpr int GEMM_SMEM = 3 * GSTAGE * 2;         // 110592 B
}

template <int MODE>
__global__ __launch_bounds__(256, 2) void k_gemm(const float* __restrict__ bias,
                                                 float* __restrict__ Cout) {
    extern __shared__ __half gsm[];

    const int tid  = threadIdx.x;
    const int warp = tid >> 5, lane = tid & 31;
    const int wm = (warp >> 2) * 64;
    const int wn = (warp & 3) * 32;
    const int gi  = lane >> 2;
    const int tig = lane & 3;
    const int m0 = blockIdx.y * GBM;
    const int n0 = blockIdx.x * GBM;

    const int lane7 = lane & 7;
    const int aRow = lane7 + ((lane & 8) ? 8 : 0);
    const int aK   = (lane & 16) ? 8 : 0;
    const int bRow = lane7 + ((lane & 16) ? 8 : 0);
    const int bK   = (lane & 8) ? 8 : 0;

    const __half* __restrict__ Ah = MODE ? g_oa : g_xa;
    const __half* __restrict__ Bh = MODE ? g_wot : g_wqkvt;

    auto issue_tile = [&](int kt, int stage) {
        __half* base = gsm + stage * GSTAGE;
        const int kk = kt * GBK;
#pragma unroll
        for (int c = 0; c < 4; ++c) {
            const int chunk = tid + c * 256;
            const int row = chunk >> 3;
            const int kc  = chunk & 7;
            const uint32_t soff = smem_u32(base + row * GLDS + kc * 8);
            cp16(soff,             Ah + (size_t)(m0 + row) * HID + kk + kc * 8);
            cp16(soff + GTILE * 2, Bh + (size_t)(n0 + row) * HID + kk + kc * 8);
        }
        CP_COMMIT();
    };

    float acc[4][4][4] = {};
    constexpr int NT = HID / GBK;   // 18

    issue_tile(0, 0);
    issue_tile(1, 1);

    int st = 0;
    for (int t = 0; t < NT; ++t) {
        if (t + 2 < NT) {
            issue_tile(t + 2, (st + 2) % 3);
            CP_WAIT(2);
        } else if (t + 1 < NT) {
            CP_WAIT(1);
        } else {
            CP_WAIT(0);
        }
        __syncthreads();

        const uint32_t uAh = smem_u32(gsm + st * GSTAGE);
        const uint32_t uBh = uAh + GTILE * 2;

#pragma unroll
        for (int ks = 0; ks < GBK; ks += 16) {
            uint32_t b[4][2];
#pragma unroll
            for (int np = 0; np < 2; ++np) {
                const uint32_t off = ((wn + np * 16 + bRow) * GLDS + ks + bK) * 2;
                ldsm4(b[2 * np][0], b[2 * np][1], b[2 * np + 1][0], b[2 * np + 1][1],
                      uBh + off);
            }
#pragma unroll
            for (int mf = 0; mf < 4; ++mf) {
                uint32_t ah[4];
                const uint32_t off = ((wm + mf * 16 + aRow) * GLDS + ks + aK) * 2;
                ldsm4(ah[0], ah[1], ah[2], ah[3], uAh + off);
#pragma unroll
                for (int nf = 0; nf < 4; ++nf)
                    mma16816(acc[mf][nf], ah, b[nf]);
            }
        }
        __syncthreads();
        st = (st + 1) % 3;
    }

    const float qscale = 0.11785113019775793f;  // 1/sqrt(72)
#pragma unroll
    for (int mf = 0; mf < 4; ++mf) {
#pragma unroll
        for (int nf = 0; nf < 4; ++nf) {
            const int row = m0 + wm + mf * 16 + gi;
            const int col = n0 + wn + nf * 8 + tig * 2;
            const float b0 = bias[col], b1 = bias[col + 1];
            float x0 = acc[mf][nf][0] + b0, y0 = acc[mf][nf][1] + b1;
            float x1 = acc[mf][nf][2] + b0, y1 = acc[mf][nf][3] + b1;
            if (MODE == 0) {
                const int which = n0 / ATT;
                const int rem = col - which * ATT;
                const int h = rem / Dd, d = rem - h * Dd;
                const int bb = row >> 10, tok = row & 1023;
                const int bh = bb * Hh + h;
                if (which < 2) {
                    if (which == 0) { x0 *= qscale; y0 *= qscale; x1 *= qscale; y1 *= qscale; }
                    __half* dst = which ? g_kh : g_qh;
                    const size_t o0 = ((size_t)bh * Nn + tok) * DP + d;
                    const size_t o1 = o0 + 8 * DP;
                    *reinterpret_cast<__half2*>(&dst[o0]) =
                        __halves2half2(__float2half(x0), __float2half(y0));
                    *reinterpret_cast<__half2*>(&dst[o1]) =
                        __halves2half2(__float2half(x1), __float2half(y1));
                } else {
                    const size_t b0o = ((size_t)bh * Dd + d) * Nn + tok;
                    const size_t b1o = b0o + Nn;
                    g_vth[b0o]     = __float2half(x0);
                    g_vth[b1o]     = __float2half(y0);
                    g_vth[b0o + 8] = __float2half(x1);
                    g_vth[b1o + 8] = __float2half(y1);
                }
            } else {
                *reinterpret_cast<float2*>(&Cout[(size_t)row * HID + col]) = make_float2(x0, y0);
                *reinterpret_cast<float2*>(&Cout[(size_t)(row + 8) * HID + col]) = make_float2(x1, y1);
            }
        }
    }
}

// ---------------------------------------------------------------------------
// Flash attention (unchanged from R15): single-pass fp16 throughout.
// ---------------------------------------------------------------------------
namespace {
constexpr int LDSK  = 88;
constexpr int LDSV  = 72;
constexpr int KROWS = 64;
constexpr int QELE  = 128 * LDSK;
constexpr int KELE  = KROWS * LDSK;
constexpr int VELE  = Dd * LDSV;
constexpr int FLASH_SMEM = (QELE + KELE + VELE) * 2;   // 44160 B
}

__global__ __launch_bounds__(256, 2) void k_flash() {
    extern __shared__ __half sm[];
    __half* sQh = sm;
    __half* sKh = sm + QELE;
    __half* sVh = sm + QELE + KELE;

    const int tid  = threadIdx.x;
    const int warp = tid >> 5, lane = tid & 31;
    const int wm  = warp * 16;
    const int gi  = lane >> 2;
    const int tig = lane & 3;
    const int bh = blockIdx.y;
    const int m0 = blockIdx.x * 128;

    const int lane7 = lane & 7;
    const int aRow = lane7 + ((lane & 8) ? 8 : 0);
    const int aK   = (lane & 16) ? 8 : 0;
    const int bRow = lane7 + ((lane & 16) ? 8 : 0);
    const int bK   = (lane & 8) ? 8 : 0;

    const uint32_t uQh = smem_u32(sQh);
    const uint32_t uKh = smem_u32(sKh);
    const uint32_t uVh = smem_u32(sVh);

    const __half* __restrict__ Qh = g_qh + (size_t)bh * Nn * DP;
    const __half* __restrict__ Kh = g_kh + (size_t)bh * Nn * DP;
    const __half* __restrict__ Vh = g_vth + (size_t)bh * Dd * Nn;

    auto issueK = [&](int kt) {
        const int nn = kt * KROWS;
#pragma unroll
        for (int c = 0; c < 3; ++c) {
            const int chunk = tid + c * 256;
            if (chunk < KROWS * 10) {
                const int row = chunk / 10;
                const int kc  = chunk - row * 10;
                cp16(smem_u32(sKh + row * LDSK + kc * 8),
                     Kh + (size_t)(nn + row) * DP + kc * 8);
            }
        }
        CP_COMMIT();
    };
    auto issueV = [&](int kt) {
        const int nn = kt * KROWS;
#pragma unroll
        for (int c = 0; c < 3; ++c) {
            const int chunk = tid + c * 256;
            if (chunk < Dd * 8) {
                const int row = chunk >> 3;
                const int kc  = chunk & 7;
                cp16(smem_u32(sVh + row * LDSV + kc * 8),
                     Vh + (size_t)row * Nn + nn + kc * 8);
            }
        }
        CP_COMMIT();
    };

    issueK(0);
#pragma unroll
    for (int c = 0; c < 5; ++c) {
        const int chunk = tid + c * 256;
        const int row = chunk / 10;
        const int kc  = chunk - row * 10;
        const size_t gq = (size_t)(m0 + row) * DP + kc * 8;
        *reinterpret_cast<uint4*>(&sQh[row * LDSK + kc * 8]) =
            *reinterpret_cast<const uint4*>(&Qh[gq]);
    }

    float m_run0 = -3.4e38f, m_run1 = -3.4e38f;
    float l_run0 = 0.f, l_run1 = 0.f;
    float o[9][4] = {};

    for (int kt = 0; kt < Nn / KROWS; ++kt) {
        CP_WAIT(0);
        __syncthreads();

        issueV(kt);

        float s[8][4];
#pragma unroll
        for (int nf = 0; nf < 8; ++nf)
            s[nf][0] = s[nf][1] = s[nf][2] = s[nf][3] = 0.f;
#pragma unroll
        for (int ks = 0; ks < DP; ks += 16) {
            uint32_t aH[4], b[2][2];
            const uint32_t aoff = ((wm + aRow) * LDSK + ks + aK) * 2;
            ldsm4(aH[0], aH[1], aH[2], aH[3], uQh + aoff);
#pragma unroll
            for (int np = 0; np < 4; ++np) {
                const uint32_t boff = ((np * 16 + bRow) * LDSK + ks + bK) * 2;
                ldsm4(b[0][0], b[0][1], b[1][0], b[1][1], uKh + boff);
                mma16816(s[2 * np],     aH, b[0]);
                mma16816(s[2 * np + 1], aH, b[1]);
            }
        }

        float mt0 = -3.4e38f, mt1 = -3.4e38f;
#pragma unroll
        for (int nf = 0; nf < 8; ++nf) {
            mt0 = fmaxf(mt0, fmaxf(s[nf][0], s[nf][1]));
            mt1 = fmaxf(mt1, fmaxf(s[nf][2], s[nf][3]));
        }
        mt0 = fmaxf(mt0, __shfl_xor_sync(0xffffffffu, mt0, 1));
        mt0 = fmaxf(mt0, __shfl_xor_sync(0xffffffffu, mt0, 2));
        mt1 = fmaxf(mt1, __shfl_xor_sync(0xffffffffu, mt1, 1));
        mt1 = fmaxf(mt1, __shfl_xor_sync(0xffffffffu, mt1, 2));
        const float mn0 = fmaxf(m_run0, mt0);
        const float mn1 = fmaxf(m_run1, mt1);
        const float sc0 = __expf(m_run0 - mn0);
        const float sc1 = __expf(m_run1 - mn1);
        m_run0 = mn0;
        m_run1 = mn1;
#pragma unroll
        for (int nf = 0; nf < 9; ++nf) {
            o[nf][0] *= sc0; o[nf][1] *= sc0;
            o[nf][2] *= sc1; o[nf][3] *= sc1;
        }

        CP_WAIT(0);
        __syncthreads();

        if (kt + 1 < Nn / KROWS) issueK(kt + 1);

        float ps0 = 0.f, ps1 = 0.f;
#pragma unroll
        for (int kc = 0; kc < 4; ++kc) {
            const int nf0 = 2 * kc, nf1 = 2 * kc + 1;
            const float p00 = __expf(s[nf0][0] - mn0), p01 = __expf(s[nf0][1] - mn0);
            const float p02 = __expf(s[nf0][2] - mn1), p03 = __expf(s[nf0][3] - mn1);
            const float p10 = __expf(s[nf1][0] - mn0), p11 = __expf(s[nf1][1] - mn0);
            const float p12 = __expf(s[nf1][2] - mn1), p13 = __expf(s[nf1][3] - mn1);
            ps0 += p00 + p01 + p10 + p11;
            ps1 += p02 + p03 + p12 + p13;
            uint32_t pH[4];
            pH[0] = pack2(p00, p01);
            pH[1] = pack2(p02, p03);
            pH[2] = pack2(p10, p11);
            pH[3] = pack2(p12, p13);

            uint32_t b[9][2];
#pragma unroll
            for (int np = 0; np < 4; ++np) {
                const uint32_t off = ((np * 16 + bRow) * LDSV + kc * 16 + bK) * 2;
                ldsm4(b[2 * np][0], b[2 * np][1], b[2 * np + 1][0], b[2 * np + 1][1], uVh + off);
            }
            {
                const uint32_t off = ((64 + lane7) * LDSV + kc * 16 + bK) * 2;
                ldsm2(b[8][0], b[8][1], uVh + off);
            }
#pragma unroll
            for (int nf = 0; nf < 9; ++nf)
                mma16816(o[nf], pH, b[nf]);
        }
        ps0 += __shfl_xor_sync(0xffffffffu, ps0, 1);
        ps0 += __shfl_xor_sync(0xffffffffu, ps0, 2);
        ps1 += __shfl_xor_sync(0xffffffffu, ps1, 1);
        ps1 += __shfl_xor_sync(0xffffffffu, ps1, 2);
        l_run0 = l_run0 * sc0 + ps0;
        l_run1 = l_run1 * sc1 + ps1;
    }

    const float inv0 = 1.0f / l_run0;
    const float inv1 = 1.0f / l_run1;
    const int b = bh >> 4;
    const int h = bh & 15;
    const int tok0 = m0 + wm + gi;
#pragma unroll
    for (int nf = 0; nf < 9; ++nf) {
        const int col = nf * 8 + tig * 2;
        const size_t o0 = ((size_t)(b * Nn + tok0)) * HID + h * Dd + col;
        const size_t o1 = ((size_t)(b * Nn + tok0 + 8)) * HID + h * Dd + col;
        *reinterpret_cast<__half2*>(&g_oa[o0]) =
            __halves2half2(__float2half(o[nf][0] * inv0), __float2half(o[nf][1] * inv0));
        *reinterpret_cast<__half2*>(&g_oa[o1]) =
            __halves2half2(__float2half(o[nf][2] * inv1), __float2half(o[nf][3] * inv1));
    }
}

// ---------------------------------------------------------------------------
extern "C" void kernel_launch(void* const* d_in, const int* in_sizes, int n_in,
                              void* d_out, int out_size) {
    const float* x     = (const float*)d_in[0];
    const float* w_qkv = (const float*)d_in[1];
    const float* b_qkv = (const float*)d_in[2];
    const float* w_out = (const float*)d_in[3];
    const float* b_out = (const float*)d_in[4];
    float* out = (float*)d_out;

    cudaFuncSetAttribute(k_flash, cudaFuncAttributeMaxDynamicSharedMemorySize, FLASH_SMEM);
    cudaFuncSetAttribute(k_gemm<0>, cudaFuncAttributeMaxDynamicSharedMemorySize, GEMM_SMEM);
    cudaFuncSetAttribute(k_gemm<1>, cudaFuncAttributeMaxDynamicSharedMemorySize, GEMM_SMEM);

    // fused prep
    k_prep<<<NB_PREP, 256>>>(x, w_qkv, w_out);

    // 1. QKV projection -> Q(scaled)/K fp16 (padded), V^T fp16
    k_gemm<0><<<dim3(QKVN / 128, MTOK / 128), 256, GEMM_SMEM>>>(b_qkv, nullptr);

    // 2. fused flash attention -> g_oa fp16
    k_flash<<<dim3(Nn / 128, BHEAD), 256, FLASH_SMEM>>>();

    // 3. output projection
    k_gemm<1><<<dim3(HID / 128, MTOK / 128), 256, GEMM_SMEM>>>(b_out, out);
}